// round 6
// baseline (speedup 1.0000x reference)
#include <cuda_runtime.h>
#include <cuda_fp16.h>
#include <math.h>

#define DIM 2048
#define NH  16
#define HD  128
#define B2  2
#define T2  2048
#define BT  4096   // B*T
#define BH  32     // B*NH

// ---------------- device scratch ----------------
__device__ __half g_Wq[DIM*DIM];
__device__ __half g_Wk[DIM*DIM];
__device__ __half g_Wv[DIM*DIM];
__device__ __half g_Wo[DIM*DIM];
__device__ __half g_Xh[BT*DIM];      // x in fp16
__device__ float  g_Qa[BH*T2*HD];    // projections fp32 [BH][T][HD]
__device__ float  g_Ka[BH*T2*HD];
__device__ float  g_Vb[BH*T2*HD];
__device__ __half g_Qh[BH*T2*HD];    // post-RoPE fp16 (scale folded)
__device__ __half g_Kh[BH*T2*HD];
__device__ __half g_Vt[BH*HD*T2];    // V transposed fp16 [BH][HD][T]
__device__ __half g_Y2[BT*DIM];      // attention out fp16 [BT][DIM]

// ---------------- helpers ----------------
__device__ __forceinline__ void mma16(float* d, const unsigned* a, const unsigned* b){
    asm volatile("mma.sync.aligned.m16n8k16.row.col.f32.f16.f16.f32 "
                 "{%0,%1,%2,%3},{%4,%5,%6,%7},{%8,%9},{%0,%1,%2,%3};"
                 : "+f"(d[0]),"+f"(d[1]),"+f"(d[2]),"+f"(d[3])
                 : "r"(a[0]),"r"(a[1]),"r"(a[2]),"r"(a[3]),"r"(b[0]),"r"(b[1]));
}
__device__ __forceinline__ void ldsm4(unsigned* r, unsigned addr){
    asm volatile("ldmatrix.sync.aligned.m8n8.x4.shared.b16 {%0,%1,%2,%3}, [%4];"
                 : "=r"(r[0]),"=r"(r[1]),"=r"(r[2]),"=r"(r[3]) : "r"(addr));
}
__device__ __forceinline__ void cpa16(unsigned saddr, const void* g){
    asm volatile("cp.async.cg.shared.global [%0], [%1], 16;" :: "r"(saddr), "l"(g));
}
__device__ __forceinline__ void cpa_commit(){
    asm volatile("cp.async.commit_group;" ::: "memory");
}
__device__ __forceinline__ void cpa_wait0(){
    asm volatile("cp.async.wait_group 0;" ::: "memory");
}

// ---------------- ternary dequant -> fp16 ----------------
__global__ void __launch_bounds__(256) dequant_kernel(
    const float* __restrict__ w, __half* __restrict__ o)
{
    int row = blockIdx.x;
    int tid = threadIdx.x;
    const float* wr = w + (size_t)row*DIM + tid*8;
    float v[8]; float s = 0.f;
    #pragma unroll
    for (int i=0;i<8;i++){ v[i]=wr[i]; s += fabsf(v[i]); }
    #pragma unroll
    for (int off=8; off; off>>=1)
        s += __shfl_xor_sync(0xffffffffu, s, off, 16);
    float scale = fmaxf(s*(1.0f/128.0f), 1e-8f);
    float inv = 1.0f/scale;
    __half* orow = o + (size_t)row*DIM + tid*8;
    #pragma unroll
    for (int i=0;i<4;i++){
        float wn0 = v[2*i]*inv, wn1 = v[2*i+1]*inv;
        float q0 = (wn0 > 0.5f) ? 1.0f : ((wn0 < -0.5f) ? -1.0f : 0.0f);
        float q1 = (wn1 > 0.5f) ? 1.0f : ((wn1 < -0.5f) ? -1.0f : 0.0f);
        *(__half2*)(orow + 2*i) = __floats2half2_rn(q0*scale, q1*scale);
    }
}

// ---------------- f32 -> f16 convert ----------------
__global__ void __launch_bounds__(256) tohalf_kernel(
    const float* __restrict__ in, __half* __restrict__ out)
{
    size_t i = ((size_t)blockIdx.x*256 + threadIdx.x)*8;
    float4 a = *(const float4*)(in + i);
    float4 b = *(const float4*)(in + i + 4);
    __half2 h[4];
    h[0]=__floats2half2_rn(a.x,a.y); h[1]=__floats2half2_rn(a.z,a.w);
    h[2]=__floats2half2_rn(b.x,b.y); h[3]=__floats2half2_rn(b.z,b.w);
    *(uint4*)(out + i) = *(uint4*)h;
}

// ---------------- fp16 GEMM, cp.async double-buffered ----------------
// C[m,n] = sum_k A[m,k]*B[n,k]; 128x128 tile, BK=64, 8 warps (2m x 4n).
#define AH 72
#define GBUF (128*AH*2)            // bytes per buffer per matrix
#define GEMM_SMEM (4*GBUF)         // 2 matrices x 2 buffers

__global__ void __launch_bounds__(256) gemm_f16_kernel(
    const __half* __restrict__ A, const __half* __restrict__ Bw,
    float* __restrict__ C, int M, int N, int K, int mode)
{
    extern __shared__ __align__(16) __half dsm[];
    int tid  = threadIdx.x;
    int bm   = blockIdx.y, bn = blockIdx.x;
    int warp = tid>>5, lane = tid&31;
    int wm   = (warp&1)<<6;
    int wn   = (warp>>1)<<5;
    int g    = lane>>2, t = lane&3;

    int arow = ((lane>>3)&1)*8 + (lane&7);
    int acol = (lane>>4)*8;
    int brow = ((lane>>4)&1)*8 + (lane&7);
    int bcol = ((lane>>3)&1)*8;
    unsigned uA = (unsigned)__cvta_generic_to_shared(dsm);
    unsigned uB = uA + 2*GBUF;

    float acc[4][4][4];
    #pragma unroll
    for(int i=0;i<4;i++)
        #pragma unroll
        for(int j=0;j<4;j++)
            #pragma unroll
            for(int r=0;r<4;r++) acc[i][j][r]=0.f;

    int lr = tid>>2;            // 0..63
    int lc = (tid&3)<<4;        // 0,16,32,48 halves
    const __half* Ag = A  + (size_t)(bm*128 + lr)*K + lc;
    const __half* Bg = Bw + (size_t)(bn*128 + lr)*K + lc;
    unsigned stoff[2][2];
    #pragma unroll
    for(int r=0;r<2;r++)
        #pragma unroll
        for(int c=0;c<2;c++)
            stoff[r][c] = ((lr + r*64)*AH + lc + c*8)*2;

    // prologue: stage 0
    #pragma unroll
    for(int r=0;r<2;r++)
        #pragma unroll
        for(int c=0;c<2;c++){
            cpa16(uA + stoff[r][c], Ag + (size_t)r*64*K + c*8);
            cpa16(uB + stoff[r][c], Bg + (size_t)r*64*K + c*8);
        }
    cpa_commit();

    int buf = 0;
    for(int k0=0; k0<K; k0+=64){
        cpa_wait0();
        __syncthreads();
        if (k0+64 < K){
            int nb = buf^1;
            #pragma unroll
            for(int r=0;r<2;r++)
                #pragma unroll
                for(int c=0;c<2;c++){
                    cpa16(uA + nb*GBUF + stoff[r][c], Ag + k0+64 + (size_t)r*64*K + c*8);
                    cpa16(uB + nb*GBUF + stoff[r][c], Bg + k0+64 + (size_t)r*64*K + c*8);
                }
            cpa_commit();
        }
        unsigned a_lane = uA + buf*GBUF + ((wm + arow)*AH + acol)*2;
        unsigned b_lane = uB + buf*GBUF + ((wn + brow)*AH + bcol)*2;
        #pragma unroll
        for(int ks=0;ks<4;ks++){
            unsigned af[4][4], bf[2][4];
            #pragma unroll
            for(int mi=0;mi<4;mi++)
                ldsm4(af[mi], a_lane + (mi*16*AH + ks*16)*2);
            #pragma unroll
            for(int p=0;p<2;p++)
                ldsm4(bf[p], b_lane + (p*16*AH + ks*16)*2);
            #pragma unroll
            for(int mi=0;mi<4;mi++)
                #pragma unroll
                for(int ni=0;ni<4;ni++)
                    mma16(acc[mi][ni], af[mi], &bf[ni>>1][(ni&1)*2]);
        }
        __syncthreads();
        buf ^= 1;
    }

    #pragma unroll
    for(int mi=0;mi<4;mi++){
        #pragma unroll
        for(int ni=0;ni<4;ni++){
            int rowa = bm*128 + wm + mi*16 + g;
            int col  = bn*128 + wn + ni*8 + 2*t;
            if (mode == 0){
                *(float2*)(C + (size_t)rowa*N + col) =
                    make_float2(acc[mi][ni][0], acc[mi][ni][1]);
                *(float2*)(C + (size_t)(rowa+8)*N + col) =
                    make_float2(acc[mi][ni][2], acc[mi][ni][3]);
            } else {
                int h = col>>7, d = col&127;
                int b0_=rowa>>11, t0_=rowa&2047;
                *(float2*)(C + ((size_t)((b0_*NH+h)*T2+t0_))*HD + d) =
                    make_float2(acc[mi][ni][0], acc[mi][ni][1]);
                int m1 = rowa+8;
                int b1_=m1>>11, t1_=m1&2047;
                *(float2*)(C + ((size_t)((b1_*NH+h)*T2+t1_))*HD + d) =
                    make_float2(acc[mi][ni][2], acc[mi][ni][3]);
            }
        }
    }
}

// ---------------- RoPE: fp32 in -> fp16 out (scale folded) ----------------
__global__ void __launch_bounds__(256) rope_kernel(
    const float* __restrict__ in, __half* __restrict__ out, float scale)
{
    size_t idx = (size_t)blockIdx.x*256 + threadIdx.x;
    int j  = (int)(idx & 63);
    int t  = (int)((idx >> 6) & 2047);
    int bh = (int)(idx >> 17);
    size_t base = ((size_t)bh*T2 + t)*HD;
    float x1 = in[base + j], x2 = in[base + j + 64];
    float invf = exp2f(-(float)j * (13.287712379549449f/64.0f));
    float ang  = (float)t * invf;
    float sn, cs; sincosf(ang, &sn, &cs);
    out[base + j]      = __float2half_rn((x1*cs - x2*sn)*scale);
    out[base + j + 64] = __float2half_rn((x1*sn + x2*cs)*scale);
}

// ---------------- V transpose: fp32 [BH][T][HD] -> fp16 [BH][HD][T] ----------
__global__ void __launch_bounds__(256) transposeTH_kernel(
    const float* __restrict__ in, __half* __restrict__ out)
{
    __shared__ float S[64][65];
    int t0 = blockIdx.x * 64;
    int d0 = blockIdx.y * 64;
    int bh = blockIdx.z;
    int tid = threadIdx.x;
    #pragma unroll
    for (int k=0;k<16;k++){
        int e = tid + k*256;
        int tl = e >> 6, dl = e & 63;
        S[tl][dl] = in[((size_t)bh*T2 + t0 + tl)*HD + d0 + dl];
    }
    __syncthreads();
    #pragma unroll
    for (int k=0;k<16;k++){
        int e = tid + k*256;
        int dl = e >> 6, tl = e & 63;
        out[((size_t)bh*HD + d0 + dl)*T2 + t0 + tl] = __float2half_rn(S[tl][dl]);
    }
}

// ---------------- fp16 flash attention, cp.async K/V pipeline ----------------
#define QH 136
#define VH 72
#define PH 72
// halves: Qs + 2x Ks + 2x Vs + Ps
#define FL_Q   (128*QH)
#define FL_K   (64*QH)
#define FL_V   (128*VH)
#define FL_P   (128*PH)
#define FL_SMEM ((FL_Q + 2*FL_K + 2*FL_V + FL_P)*2)

__global__ void __launch_bounds__(256) flash3_kernel(
    const __half* __restrict__ Q, const __half* __restrict__ K,
    const __half* __restrict__ Vt, __half* __restrict__ Y2)
{
    extern __shared__ __align__(16) __half smh[];
    __half* Qs = smh;                      // [128][136]
    __half* Ks = Qs + FL_Q;                // 2 x [64][136]
    __half* Vs = Ks + 2*FL_K;              // 2 x [128][72]
    __half* Ps = Vs + 2*FL_V;              // [128][72]

    int qb  = (int)(gridDim.x - 1 - blockIdx.x);
    int bh  = blockIdx.y;
    int tid = threadIdx.x;
    int warp = tid >> 5, lane = tid & 31;
    int g = lane >> 2, t = lane & 3;

    int arow = ((lane>>3)&1)*8 + (lane&7);
    int acol = (lane>>4)*8;
    int brow = ((lane>>4)&1)*8 + (lane&7);
    int bcol = ((lane>>3)&1)*8;
    unsigned uQ = (unsigned)__cvta_generic_to_shared(Qs);
    unsigned uK = (unsigned)__cvta_generic_to_shared(Ks);
    unsigned uV = (unsigned)__cvta_generic_to_shared(Vs);
    unsigned uP = (unsigned)__cvta_generic_to_shared(Ps);
    unsigned q_lane = uQ + ((warp*16 + arow)*QH + acol)*2;
    unsigned p_lane = uP + ((warp*16 + arow)*PH + acol)*2;

    const __half* qg = Q  + ((size_t)bh*T2 + qb*128)*HD;
    const __half* kg = K  + (size_t)bh*T2*HD;
    const __half* vg = Vt + (size_t)bh*HD*T2;

    // K/V load lane mapping
    int kr = tid >> 4, kc = (tid & 15) << 3;   // 4 iters: rows kr + it*16
    int vd = tid >> 3, vc = (tid & 7) << 3;    // 4 iters: d = vd + it*32

    // prologue: Q + tile 0 in one group
    #pragma unroll
    for (int it=0; it<8; it++){
        int idx = tid + it*256;
        int r = idx >> 4, c = (idx & 15) << 3;
        cpa16(uQ + (r*QH + c)*2, qg + (size_t)r*HD + c);
    }
    #pragma unroll
    for (int it=0; it<4; it++)
        cpa16(uK + ((kr + it*16)*QH + kc)*2, kg + (size_t)(kr + it*16)*HD + kc);
    #pragma unroll
    for (int it=0; it<4; it++)
        cpa16(uV + ((vd + it*32)*VH + vc)*2, vg + (size_t)(vd + it*32)*T2 + vc);
    cpa_commit();

    float m0 = -1e30f, m1 = -1e30f, l0 = 0.f, l1 = 0.f;
    float o[16][4];
    #pragma unroll
    for (int i=0;i<16;i++)
        #pragma unroll
        for (int r=0;r<4;r++) o[i][r]=0.f;

    int prow = warp*16 + g;
    int nkb = 2*qb + 2;

    for (int kb=0; kb<nkb; kb++){
        int buf = kb & 1;
        cpa_wait0();
        __syncthreads();
        if (kb+1 < nkb){
            int nb = buf^1;
            #pragma unroll
            for (int it=0; it<4; it++)
                cpa16(uK + (nb*FL_K + (kr + it*16)*QH + kc)*2,
                      kg + (size_t)((kb+1)*64 + kr + it*16)*HD + kc);
            #pragma unroll
            for (int it=0; it<4; it++)
                cpa16(uV + (nb*FL_V + (vd + it*32)*VH + vc)*2,
                      vg + (size_t)(vd + it*32)*T2 + (kb+1)*64 + vc);
            cpa_commit();
        }
        unsigned k_lane = uK + buf*FL_K*2 + (brow*QH + bcol)*2;
        unsigned v_lane = uV + buf*FL_V*2 + (brow*VH + bcol)*2;

        // S = Q K^T : per warp 16 x 64, k=128 (8 k16-steps)
        float s[8][4];
        #pragma unroll
        for (int ni=0;ni<8;ni++)
            #pragma unroll
            for (int r=0;r<4;r++) s[ni][r]=0.f;
        #pragma unroll
        for (int ks=0; ks<8; ks++){
            unsigned af[4], kf[4][4];
            ldsm4(af, q_lane + ks*32);
            #pragma unroll
            for (int p=0;p<4;p++)
                ldsm4(kf[p], k_lane + (p*16*QH + ks*16)*2);
            #pragma unroll
            for (int ni=0;ni<8;ni++)
                mma16(s[ni], af, &kf[ni>>1][(ni&1)*2]);
        }

        // causal mask
        if (kb >= 2*qb){
            int q0 = qb*128 + prow, q1 = q0 + 8;
            #pragma unroll
            for (int ni=0;ni<8;ni++){
                int k0 = kb*64 + ni*8 + 2*t;
                if (k0   > q0) s[ni][0] = -1e30f;
                if (k0+1 > q0) s[ni][1] = -1e30f;
                if (k0   > q1) s[ni][2] = -1e30f;
                if (k0+1 > q1) s[ni][3] = -1e30f;
            }
        }

        // online softmax
        float mx0 = -1e30f, mx1 = -1e30f;
        #pragma unroll
        for (int ni=0;ni<8;ni++){
            mx0 = fmaxf(mx0, fmaxf(s[ni][0], s[ni][1]));
            mx1 = fmaxf(mx1, fmaxf(s[ni][2], s[ni][3]));
        }
        #pragma unroll
        for (int off=1; off<4; off<<=1){
            mx0 = fmaxf(mx0, __shfl_xor_sync(0xffffffffu, mx0, off, 4));
            mx1 = fmaxf(mx1, __shfl_xor_sync(0xffffffffu, mx1, off, 4));
        }
        float nm0 = fmaxf(m0, mx0), nm1 = fmaxf(m1, mx1);
        float a0 = __expf(m0 - nm0), a1 = __expf(m1 - nm1);
        m0 = nm0; m1 = nm1;
        float sum0 = 0.f, sum1 = 0.f;
        #pragma unroll
        for (int ni=0;ni<8;ni++){
            s[ni][0] = __expf(s[ni][0]-nm0); sum0 += s[ni][0];
            s[ni][1] = __expf(s[ni][1]-nm0); sum0 += s[ni][1];
            s[ni][2] = __expf(s[ni][2]-nm1); sum1 += s[ni][2];
            s[ni][3] = __expf(s[ni][3]-nm1); sum1 += s[ni][3];
        }
        #pragma unroll
        for (int off=1; off<4; off<<=1){
            sum0 += __shfl_xor_sync(0xffffffffu, sum0, off, 4);
            sum1 += __shfl_xor_sync(0xffffffffu, sum1, off, 4);
        }
        l0 = l0*a0 + sum0;
        l1 = l1*a1 + sum1;
        #pragma unroll
        for (int ti=0;ti<16;ti++){
            o[ti][0]*=a0; o[ti][1]*=a0; o[ti][2]*=a1; o[ti][3]*=a1;
        }

        // P -> smem (fp16)
        #pragma unroll
        for (int ni=0;ni<8;ni++){
            int cc = ni*8 + 2*t;
            *(__half2*)&Ps[prow*PH + cc]     = __floats2half2_rn(s[ni][0], s[ni][1]);
            *(__half2*)&Ps[(prow+8)*PH + cc] = __floats2half2_rn(s[ni][2], s[ni][3]);
        }
        __syncwarp();

        // O += P V : per warp 16 x 128, k=64 (4 k16-steps)
        #pragma unroll
        for (int ks=0; ks<4; ks++){
            unsigned af[4], vf[8][4];
            ldsm4(af, p_lane + ks*32);
            #pragma unroll
            for (int p=0;p<8;p++)
                ldsm4(vf[p], v_lane + (p*16*VH + ks*16)*2);
            #pragma unroll
            for (int ti=0;ti<16;ti++)
                mma16(o[ti], af, &vf[ti>>1][(ti&1)*2]);
        }
        __syncthreads();
    }

    // write to [BT][DIM] fp16
    float i0 = 1.0f/l0, i1 = 1.0f/l1;
    int trow = qb*128 + prow;
    int b_ = bh >> 4, h = bh & 15;
    __half* yr = Y2 + ((size_t)b_*T2)*DIM + h*HD;
    #pragma unroll
    for (int ti=0;ti<16;ti++){
        int col = ti*8 + 2*t;
        *(__half2*)(yr + (size_t)trow*DIM + col) =
            __floats2half2_rn(o[ti][0]*i0, o[ti][1]*i0);
        *(__half2*)(yr + (size_t)(trow+8)*DIM + col) =
            __floats2half2_rn(o[ti][2]*i1, o[ti][3]*i1);
    }
}

// ---------------- launch ----------------
extern "C" void kernel_launch(void* const* d_in, const int* in_sizes, int n_in,
                              void* d_out, int out_size)
{
    const float* x  = (const float*)d_in[0];
    const float* wq = (const float*)d_in[1];
    const float* wk = (const float*)d_in[2];
    const float* wv = (const float*)d_in[3];
    const float* wo = (const float*)d_in[4];
    float* out = (float*)d_out;

    __half *Wq,*Wk,*Wv,*Wo,*Xh,*Qh,*Kh,*Vt,*Y2;
    float *Qa,*Ka,*Vb;
    cudaGetSymbolAddress((void**)&Wq, g_Wq);
    cudaGetSymbolAddress((void**)&Wk, g_Wk);
    cudaGetSymbolAddress((void**)&Wv, g_Wv);
    cudaGetSymbolAddress((void**)&Wo, g_Wo);
    cudaGetSymbolAddress((void**)&Xh, g_Xh);
    cudaGetSymbolAddress((void**)&Qa, g_Qa);
    cudaGetSymbolAddress((void**)&Ka, g_Ka);
    cudaGetSymbolAddress((void**)&Vb, g_Vb);
    cudaGetSymbolAddress((void**)&Qh, g_Qh);
    cudaGetSymbolAddress((void**)&Kh, g_Kh);
    cudaGetSymbolAddress((void**)&Vt, g_Vt);
    cudaGetSymbolAddress((void**)&Y2, g_Y2);

    cudaFuncSetAttribute(gemm_f16_kernel,
        cudaFuncAttributeMaxDynamicSharedMemorySize, GEMM_SMEM);
    cudaFuncSetAttribute(flash3_kernel,
        cudaFuncAttributeMaxDynamicSharedMemorySize, FL_SMEM);

    dequant_kernel<<<DIM,256>>>(wq, Wq);
    dequant_kernel<<<DIM,256>>>(wk, Wk);
    dequant_kernel<<<DIM,256>>>(wv, Wv);
    dequant_kernel<<<DIM,256>>>(wo, Wo);
    tohalf_kernel<<<(BT*DIM)/2048, 256>>>(x, Xh);

    dim3 gg(DIM/128, BT/128);
    gemm_f16_kernel<<<gg,256,GEMM_SMEM>>>(Xh, Wq, Qa, BT, DIM, DIM, 1);
    gemm_f16_kernel<<<gg,256,GEMM_SMEM>>>(Xh, Wk, Ka, BT, DIM, DIM, 1);
    gemm_f16_kernel<<<gg,256,GEMM_SMEM>>>(Xh, Wv, Vb, BT, DIM, DIM, 1);

    rope_kernel<<<(BH*T2*64)/256, 256>>>(Qa, Qh, 0.08838834764831845f);
    rope_kernel<<<(BH*T2*64)/256, 256>>>(Ka, Kh, 1.0f);

    transposeTH_kernel<<<dim3(T2/64, HD/64, BH), 256>>>(Vb, Vt);

    flash3_kernel<<<dim3(T2/128, BH), 256, FL_SMEM>>>(Qh, Kh, Vt, Y2);

    gemm_f16_kernel<<<gg,256,GEMM_SMEM>>>(Y2, Wo, out, BT, DIM, DIM, 0);
}

// round 9
// speedup vs baseline: 1.6057x; 1.6057x over previous
#include <cuda_runtime.h>
#include <cuda_fp16.h>
#include <math.h>

#define DIM 2048
#define NH  16
#define HD  128
#define B2  2
#define T2  2048
#define BT  4096   // B*T
#define BH  32     // B*NH

// ---------------- device scratch ----------------
__device__ __half g_Wq[DIM*DIM];
__device__ __half g_Wk[DIM*DIM];
__device__ __half g_Wv[DIM*DIM];
__device__ __half g_Wo[DIM*DIM];
__device__ __half g_Xh[BT*DIM];      // x in fp16
__device__ float  g_Qa[BH*T2*HD];    // projections fp32 [BH][T][HD]
__device__ float  g_Ka[BH*T2*HD];
__device__ float  g_Vb[BH*T2*HD];
__device__ __half g_Qh[BH*T2*HD];    // post-RoPE fp16 (scale folded)
__device__ __half g_Kh[BH*T2*HD];
__device__ __half g_Vt[BH*HD*T2];    // V transposed fp16 [BH][HD][T]
__device__ __half g_Y2[BT*DIM];      // attention out fp16 [BT][DIM]

// ---------------- helpers ----------------
__device__ __forceinline__ void mma16(float* d, const unsigned* a, const unsigned* b){
    asm volatile("mma.sync.aligned.m16n8k16.row.col.f32.f16.f16.f32 "
                 "{%0,%1,%2,%3},{%4,%5,%6,%7},{%8,%9},{%0,%1,%2,%3};"
                 : "+f"(d[0]),"+f"(d[1]),"+f"(d[2]),"+f"(d[3])
                 : "r"(a[0]),"r"(a[1]),"r"(a[2]),"r"(a[3]),"r"(b[0]),"r"(b[1]));
}
__device__ __forceinline__ void ldsm4(unsigned* r, unsigned addr){
    asm volatile("ldmatrix.sync.aligned.m8n8.x4.shared.b16 {%0,%1,%2,%3}, [%4];"
                 : "=r"(r[0]),"=r"(r[1]),"=r"(r[2]),"=r"(r[3]) : "r"(addr));
}

// ---------------- ternary dequant -> fp16 ----------------
__global__ void __launch_bounds__(256) dequant_kernel(
    const float* __restrict__ w, __half* __restrict__ o)
{
    int row = blockIdx.x;
    int tid = threadIdx.x;
    const float* wr = w + (size_t)row*DIM + tid*8;
    float v[8]; float s = 0.f;
    #pragma unroll
    for (int i=0;i<8;i++){ v[i]=wr[i]; s += fabsf(v[i]); }
    #pragma unroll
    for (int off=8; off; off>>=1)
        s += __shfl_xor_sync(0xffffffffu, s, off, 16);
    float scale = fmaxf(s*(1.0f/128.0f), 1e-8f);
    float inv = 1.0f/scale;
    __half* orow = o + (size_t)row*DIM + tid*8;
    #pragma unroll
    for (int i=0;i<4;i++){
        float wn0 = v[2*i]*inv, wn1 = v[2*i+1]*inv;
        float q0 = (wn0 > 0.5f) ? 1.0f : ((wn0 < -0.5f) ? -1.0f : 0.0f);
        float q1 = (wn1 > 0.5f) ? 1.0f : ((wn1 < -0.5f) ? -1.0f : 0.0f);
        *(__half2*)(orow + 2*i) = __floats2half2_rn(q0*scale, q1*scale);
    }
}

// ---------------- f32 -> f16 convert ----------------
__global__ void __launch_bounds__(256) tohalf_kernel(
    const float* __restrict__ in, __half* __restrict__ out)
{
    size_t i = ((size_t)blockIdx.x*256 + threadIdx.x)*8;
    float4 a = *(const float4*)(in + i);
    float4 b = *(const float4*)(in + i + 4);
    __half2 h[4];
    h[0]=__floats2half2_rn(a.x,a.y); h[1]=__floats2half2_rn(a.z,a.w);
    h[2]=__floats2half2_rn(b.x,b.y); h[3]=__floats2half2_rn(b.z,b.w);
    *(uint4*)(out + i) = *(uint4*)h;
}

// ---------------- fp16 GEMM, double-buffered smem, single sync/iter ---------
// C[m,n] = sum_k A[m,k]*B[n,k]; 128x128 tile, BK=64, 8 warps (2m x 4n).
#define AH 72
#define GHALF (128*AH)             // halves per matrix per buffer
#define GEMM_SMEM (4*GHALF*2)      // 2 matrices x 2 buffers, bytes

__global__ void __launch_bounds__(256) gemm_f16_kernel(
    const __half* __restrict__ A, const __half* __restrict__ Bw,
    float* __restrict__ C, int M, int N, int K, int mode)
{
    extern __shared__ __align__(16) __half dsm[];
    __half* As = dsm;                 // 2 x [128][72]
    __half* Bs = dsm + 2*GHALF;       // 2 x [128][72]
    int tid  = threadIdx.x;
    int bm   = blockIdx.y, bn = blockIdx.x;
    int warp = tid>>5, lane = tid&31;
    int wm   = (warp&1)<<6;
    int wn   = (warp>>1)<<5;
    int g    = lane>>2, t = lane&3;

    int arow = ((lane>>3)&1)*8 + (lane&7);
    int acol = (lane>>4)*8;
    int brow = ((lane>>4)&1)*8 + (lane&7);
    int bcol = ((lane>>3)&1)*8;
    unsigned uA = (unsigned)__cvta_generic_to_shared(As);
    unsigned uB = (unsigned)__cvta_generic_to_shared(Bs);

    float acc[4][4][4];
    #pragma unroll
    for(int i=0;i<4;i++)
        #pragma unroll
        for(int j=0;j<4;j++)
            #pragma unroll
            for(int r=0;r<4;r++) acc[i][j][r]=0.f;

    int lr = tid>>2;            // 0..63
    int lc = (tid&3)<<4;        // 0,16,32,48 halves
    const __half* Ag = A  + (size_t)(bm*128 + lr)*K + lc;
    const __half* Bg = Bw + (size_t)(bn*128 + lr)*K + lc;
    int soff[2][2];
    #pragma unroll
    for(int r=0;r<2;r++)
        #pragma unroll
        for(int c=0;c<2;c++)
            soff[r][c] = (lr + r*64)*AH + lc + c*8;

    uint4 av[2][2], bv[2][2];
    // prologue: chunk 0 -> regs -> buf 0
    #pragma unroll
    for(int r=0;r<2;r++)
        #pragma unroll
        for(int c=0;c<2;c++){
            av[r][c] = *(const uint4*)(Ag + (size_t)r*64*K + c*8);
            bv[r][c] = *(const uint4*)(Bg + (size_t)r*64*K + c*8);
        }
    #pragma unroll
    for(int r=0;r<2;r++)
        #pragma unroll
        for(int c=0;c<2;c++){
            *(uint4*)&As[soff[r][c]] = av[r][c];
            *(uint4*)&Bs[soff[r][c]] = bv[r][c];
        }

    int buf = 0;
    for(int k0=0; k0<K; k0+=64){
        __syncthreads();           // buf ready; alt-buf readers done
        bool more = (k0+64 < K);
        if (more){
            #pragma unroll
            for(int r=0;r<2;r++)
                #pragma unroll
                for(int c=0;c<2;c++){
                    av[r][c] = *(const uint4*)(Ag + k0+64 + (size_t)r*64*K + c*8);
                    bv[r][c] = *(const uint4*)(Bg + k0+64 + (size_t)r*64*K + c*8);
                }
        }
        unsigned a_lane = uA + (buf*GHALF + (wm + arow)*AH + acol)*2;
        unsigned b_lane = uB + (buf*GHALF + (wn + brow)*AH + bcol)*2;
        #pragma unroll
        for(int ks=0;ks<4;ks++){
            unsigned af[4][4], bf[2][4];
            #pragma unroll
            for(int mi=0;mi<4;mi++)
                ldsm4(af[mi], a_lane + (mi*16*AH + ks*16)*2);
            #pragma unroll
            for(int p=0;p<2;p++)
                ldsm4(bf[p], b_lane + (p*16*AH + ks*16)*2);
            #pragma unroll
            for(int mi=0;mi<4;mi++)
                #pragma unroll
                for(int ni=0;ni<4;ni++)
                    mma16(acc[mi][ni], af[mi], &bf[ni>>1][(ni&1)*2]);
        }
        if (more){
            int nb = buf^1;
            #pragma unroll
            for(int r=0;r<2;r++)
                #pragma unroll
                for(int c=0;c<2;c++){
                    *(uint4*)&As[nb*GHALF + soff[r][c]] = av[r][c];
                    *(uint4*)&Bs[nb*GHALF + soff[r][c]] = bv[r][c];
                }
        }
        buf ^= 1;
    }

    #pragma unroll
    for(int mi=0;mi<4;mi++){
        #pragma unroll
        for(int ni=0;ni<4;ni++){
            int rowa = bm*128 + wm + mi*16 + g;
            int col  = bn*128 + wn + ni*8 + 2*t;
            if (mode == 0){
                *(float2*)(C + (size_t)rowa*N + col) =
                    make_float2(acc[mi][ni][0], acc[mi][ni][1]);
                *(float2*)(C + (size_t)(rowa+8)*N + col) =
                    make_float2(acc[mi][ni][2], acc[mi][ni][3]);
            } else {
                int h = col>>7, d = col&127;
                int b0_=rowa>>11, t0_=rowa&2047;
                *(float2*)(C + ((size_t)((b0_*NH+h)*T2+t0_))*HD + d) =
                    make_float2(acc[mi][ni][0], acc[mi][ni][1]);
                int m1 = rowa+8;
                int b1_=m1>>11, t1_=m1&2047;
                *(float2*)(C + ((size_t)((b1_*NH+h)*T2+t1_))*HD + d) =
                    make_float2(acc[mi][ni][2], acc[mi][ni][3]);
            }
        }
    }
}

// ---------------- RoPE: fp32 in -> fp16 out (scale folded) ----------------
__global__ void __launch_bounds__(256) rope_kernel(
    const float* __restrict__ in, __half* __restrict__ out, float scale)
{
    size_t idx = (size_t)blockIdx.x*256 + threadIdx.x;
    int j  = (int)(idx & 63);
    int t  = (int)((idx >> 6) & 2047);
    int bh = (int)(idx >> 17);
    size_t base = ((size_t)bh*T2 + t)*HD;
    float x1 = in[base + j], x2 = in[base + j + 64];
    float invf = exp2f(-(float)j * (13.287712379549449f/64.0f));
    float ang  = (float)t * invf;
    float sn, cs; sincosf(ang, &sn, &cs);
    out[base + j]      = __float2half_rn((x1*cs - x2*sn)*scale);
    out[base + j + 64] = __float2half_rn((x1*sn + x2*cs)*scale);
}

// ---------------- V transpose: fp32 [BH][T][HD] -> fp16 [BH][HD][T] ----------
__global__ void __launch_bounds__(256) transposeTH_kernel(
    const float* __restrict__ in, __half* __restrict__ out)
{
    __shared__ float S[64][65];
    int t0 = blockIdx.x * 64;
    int d0 = blockIdx.y * 64;
    int bh = blockIdx.z;
    int tid = threadIdx.x;
    #pragma unroll
    for (int k=0;k<16;k++){
        int e = tid + k*256;
        int tl = e >> 6, dl = e & 63;
        S[tl][dl] = in[((size_t)bh*T2 + t0 + tl)*HD + d0 + dl];
    }
    __syncthreads();
    #pragma unroll
    for (int k=0;k<16;k++){
        int e = tid + k*256;
        int dl = e >> 6, tl = e & 63;
        out[((size_t)bh*HD + d0 + dl)*T2 + t0 + tl] = __float2half_rn(S[tl][dl]);
    }
}

// ---------------- fp16 flash attention, double-buffered K/V ----------------
#define QH 136
#define VH 72
#define PH 72
#define FL_Q (128*QH)
#define FL_K (64*QH)
#define FL_V (128*VH)
#define FL_P (128*PH)
#define FL_SMEM ((FL_Q + 2*FL_K + 2*FL_V + FL_P)*2)

__global__ void __launch_bounds__(256) flash3_kernel(
    const __half* __restrict__ Q, const __half* __restrict__ K,
    const __half* __restrict__ Vt, __half* __restrict__ Y2)
{
    extern __shared__ __align__(16) __half smh[];
    __half* Qs = smh;                // [128][136]
    __half* Ks = Qs + FL_Q;          // 2 x [64][136]
    __half* Vs = Ks + 2*FL_K;        // 2 x [128][72]
    __half* Ps = Vs + 2*FL_V;        // [128][72]

    int qb  = (int)(gridDim.x - 1 - blockIdx.x);
    int bh  = blockIdx.y;
    int tid = threadIdx.x;
    int warp = tid >> 5, lane = tid & 31;
    int g = lane >> 2, t = lane & 3;

    int arow = ((lane>>3)&1)*8 + (lane&7);
    int acol = (lane>>4)*8;
    int brow = ((lane>>4)&1)*8 + (lane&7);
    int bcol = ((lane>>3)&1)*8;
    unsigned uQ = (unsigned)__cvta_generic_to_shared(Qs);
    unsigned uK = (unsigned)__cvta_generic_to_shared(Ks);
    unsigned uV = (unsigned)__cvta_generic_to_shared(Vs);
    unsigned uP = (unsigned)__cvta_generic_to_shared(Ps);
    unsigned q_lane = uQ + ((warp*16 + arow)*QH + acol)*2;
    unsigned p_lane = uP + ((warp*16 + arow)*PH + acol)*2;

    const __half* qg = Q  + ((size_t)bh*T2 + qb*128)*HD;
    const __half* kg = K  + (size_t)bh*T2*HD;
    const __half* vg = Vt + (size_t)bh*HD*T2;

    // K/V staging lane mapping (4 uint4 each per thread)
    int kr = tid >> 4, kc = (tid & 15) << 3;   // rows kr + it*16
    int vd = tid >> 3, vc = (tid & 7) << 3;    // d = vd + it*32

    // stage Q
    #pragma unroll
    for (int it=0; it<8; it++){
        int idx = tid + it*256;
        int r = idx >> 4, c = (idx & 15) << 3;
        *(uint4*)&Qs[r*QH + c] = *(const uint4*)(qg + (size_t)r*HD + c);
    }
    // prologue: K/V tile 0 -> regs -> buf 0
    uint4 kvreg[8];
    #pragma unroll
    for (int it=0; it<4; it++)
        kvreg[it] = *(const uint4*)(kg + (size_t)(kr + it*16)*HD + kc);
    #pragma unroll
    for (int it=0; it<4; it++)
        kvreg[4+it] = *(const uint4*)(vg + (size_t)(vd + it*32)*T2 + vc);
    #pragma unroll
    for (int it=0; it<4; it++)
        *(uint4*)&Ks[(kr + it*16)*QH + kc] = kvreg[it];
    #pragma unroll
    for (int it=0; it<4; it++)
        *(uint4*)&Vs[(vd + it*32)*VH + vc] = kvreg[4+it];

    float m0 = -1e30f, m1 = -1e30f, l0 = 0.f, l1 = 0.f;
    float o[16][4];
    #pragma unroll
    for (int i=0;i<16;i++)
        #pragma unroll
        for (int r=0;r<4;r++) o[i][r]=0.f;

    int prow = warp*16 + g;
    int nkb = 2*qb + 2;

    for (int kb=0; kb<nkb; kb++){
        int buf = kb & 1;
        __syncthreads();           // buf ready; alt-buf readers done
        bool more = (kb+1 < nkb);
        if (more){
            #pragma unroll
            for (int it=0; it<4; it++)
                kvreg[it] = *(const uint4*)(kg + (size_t)((kb+1)*64 + kr + it*16)*HD + kc);
            #pragma unroll
            for (int it=0; it<4; it++)
                kvreg[4+it] = *(const uint4*)(vg + (size_t)(vd + it*32)*T2 + (kb+1)*64 + vc);
        }
        unsigned k_lane = uK + (buf*FL_K + brow*QH + bcol)*2;
        unsigned v_lane = uV + (buf*FL_V + brow*VH + bcol)*2;

        // S = Q K^T : per warp 16 x 64, k=128 (8 k16-steps)
        float s[8][4];
        #pragma unroll
        for (int ni=0;ni<8;ni++)
            #pragma unroll
            for (int r=0;r<4;r++) s[ni][r]=0.f;
        #pragma unroll
        for (int ks=0; ks<8; ks++){
            unsigned af[4], kf[4][4];
            ldsm4(af, q_lane + ks*32);
            #pragma unroll
            for (int p=0;p<4;p++)
                ldsm4(kf[p], k_lane + (p*16*QH + ks*16)*2);
            #pragma unroll
            for (int ni=0;ni<8;ni++)
                mma16(s[ni], af, &kf[ni>>1][(ni&1)*2]);
        }

        // causal mask
        if (kb >= 2*qb){
            int q0 = qb*128 + prow, q1 = q0 + 8;
            #pragma unroll
            for (int ni=0;ni<8;ni++){
                int k0 = kb*64 + ni*8 + 2*t;
                if (k0   > q0) s[ni][0] = -1e30f;
                if (k0+1 > q0) s[ni][1] = -1e30f;
                if (k0   > q1) s[ni][2] = -1e30f;
                if (k0+1 > q1) s[ni][3] = -1e30f;
            }
        }

        // online softmax
        float mx0 = -1e30f, mx1 = -1e30f;
        #pragma unroll
        for (int ni=0;ni<8;ni++){
            mx0 = fmaxf(mx0, fmaxf(s[ni][0], s[ni][1]));
            mx1 = fmaxf(mx1, fmaxf(s[ni][2], s[ni][3]));
        }
        #pragma unroll
        for (int off=1; off<4; off<<=1){
            mx0 = fmaxf(mx0, __shfl_xor_sync(0xffffffffu, mx0, off, 4));
            mx1 = fmaxf(mx1, __shfl_xor_sync(0xffffffffu, mx1, off, 4));
        }
        float nm0 = fmaxf(m0, mx0), nm1 = fmaxf(m1, mx1);
        float a0 = __expf(m0 - nm0), a1 = __expf(m1 - nm1);
        m0 = nm0; m1 = nm1;
        float sum0 = 0.f, sum1 = 0.f;
        #pragma unroll
        for (int ni=0;ni<8;ni++){
            s[ni][0] = __expf(s[ni][0]-nm0); sum0 += s[ni][0];
            s[ni][1] = __expf(s[ni][1]-nm0); sum0 += s[ni][1];
            s[ni][2] = __expf(s[ni][2]-nm1); sum1 += s[ni][2];
            s[ni][3] = __expf(s[ni][3]-nm1); sum1 += s[ni][3];
        }
        #pragma unroll
        for (int off=1; off<4; off<<=1){
            sum0 += __shfl_xor_sync(0xffffffffu, sum0, off, 4);
            sum1 += __shfl_xor_sync(0xffffffffu, sum1, off, 4);
        }
        l0 = l0*a0 + sum0;
        l1 = l1*a1 + sum1;
        #pragma unroll
        for (int ti=0;ti<16;ti++){
            o[ti][0]*=a0; o[ti][1]*=a0; o[ti][2]*=a1; o[ti][3]*=a1;
        }

        // P -> smem (fp16), warp-private rows
        #pragma unroll
        for (int ni=0;ni<8;ni++){
            int cc = ni*8 + 2*t;
            *(__half2*)&Ps[prow*PH + cc]     = __floats2half2_rn(s[ni][0], s[ni][1]);
            *(__half2*)&Ps[(prow+8)*PH + cc] = __floats2half2_rn(s[ni][2], s[ni][3]);
        }
        __syncwarp();

        // O += P V : per warp 16 x 128, k=64 (4 k16-steps)
        #pragma unroll
        for (int ks=0; ks<4; ks++){
            unsigned af[4], vf[8][4];
            ldsm4(af, p_lane + ks*32);
            #pragma unroll
            for (int p=0;p<8;p++)
                ldsm4(vf[p], v_lane + (p*16*VH + ks*16)*2);
            #pragma unroll
            for (int ti=0;ti<16;ti++)
                mma16(o[ti], af, &vf[ti>>1][(ti&1)*2]);
        }

        // stage next K/V into alternate buffer
        if (more){
            int nb = buf^1;
            #pragma unroll
            for (int it=0; it<4; it++)
                *(uint4*)&Ks[nb*FL_K + (kr + it*16)*QH + kc] = kvreg[it];
            #pragma unroll
            for (int it=0; it<4; it++)
                *(uint4*)&Vs[nb*FL_V + (vd + it*32)*VH + vc] = kvreg[4+it];
        }
    }

    // write to [BT][DIM] fp16
    float i0 = 1.0f/l0, i1 = 1.0f/l1;
    int trow = qb*128 + prow;
    int b_ = bh >> 4, h = bh & 15;
    __half* yr = Y2 + ((size_t)b_*T2)*DIM + h*HD;
    #pragma unroll
    for (int ti=0;ti<16;ti++){
        int col = ti*8 + 2*t;
        *(__half2*)(yr + (size_t)trow*DIM + col) =
            __floats2half2_rn(o[ti][0]*i0, o[ti][1]*i0);
        *(__half2*)(yr + (size_t)(trow+8)*DIM + col) =
            __floats2half2_rn(o[ti][2]*i1, o[ti][3]*i1);
    }
}

// ---------------- launch ----------------
extern "C" void kernel_launch(void* const* d_in, const int* in_sizes, int n_in,
                              void* d_out, int out_size)
{
    const float* x  = (const float*)d_in[0];
    const float* wq = (const float*)d_in[1];
    const float* wk = (const float*)d_in[2];
    const float* wv = (const float*)d_in[3];
    const float* wo = (const float*)d_in[4];
    float* out = (float*)d_out;

    __half *Wq,*Wk,*Wv,*Wo,*Xh,*Qh,*Kh,*Vt,*Y2;
    float *Qa,*Ka,*Vb;
    cudaGetSymbolAddress((void**)&Wq, g_Wq);
    cudaGetSymbolAddress((void**)&Wk, g_Wk);
    cudaGetSymbolAddress((void**)&Wv, g_Wv);
    cudaGetSymbolAddress((void**)&Wo, g_Wo);
    cudaGetSymbolAddress((void**)&Xh, g_Xh);
    cudaGetSymbolAddress((void**)&Qa, g_Qa);
    cudaGetSymbolAddress((void**)&Ka, g_Ka);
    cudaGetSymbolAddress((void**)&Vb, g_Vb);
    cudaGetSymbolAddress((void**)&Qh, g_Qh);
    cudaGetSymbolAddress((void**)&Kh, g_Kh);
    cudaGetSymbolAddress((void**)&Vt, g_Vt);
    cudaGetSymbolAddress((void**)&Y2, g_Y2);

    cudaFuncSetAttribute(gemm_f16_kernel,
        cudaFuncAttributeMaxDynamicSharedMemorySize, GEMM_SMEM);
    cudaFuncSetAttribute(flash3_kernel,
        cudaFuncAttributeMaxDynamicSharedMemorySize, FL_SMEM);

    dequant_kernel<<<DIM,256>>>(wq, Wq);
    dequant_kernel<<<DIM,256>>>(wk, Wk);
    dequant_kernel<<<DIM,256>>>(wv, Wv);
    dequant_kernel<<<DIM,256>>>(wo, Wo);
    tohalf_kernel<<<(BT*DIM)/2048, 256>>>(x, Xh);

    dim3 gg(DIM/128, BT/128);
    gemm_f16_kernel<<<gg,256,GEMM_SMEM>>>(Xh, Wq, Qa, BT, DIM, DIM, 1);
    gemm_f16_kernel<<<gg,256,GEMM_SMEM>>>(Xh, Wk, Ka, BT, DIM, DIM, 1);
    gemm_f16_kernel<<<gg,256,GEMM_SMEM>>>(Xh, Wv, Vb, BT, DIM, DIM, 1);

    rope_kernel<<<(BH*T2*64)/256, 256>>>(Qa, Qh, 0.08838834764831845f);
    rope_kernel<<<(BH*T2*64)/256, 256>>>(Ka, Kh, 1.0f);

    transposeTH_kernel<<<dim3(T2/64, HD/64, BH), 256>>>(Vb, Vt);

    flash3_kernel<<<dim3(T2/128, BH), 256, FL_SMEM>>>(Qh, Kh, Vt, Y2);

    gemm_f16_kernel<<<gg,256,GEMM_SMEM>>>(Y2, Wo, out, BT, DIM, DIM, 0);
}

// round 10
// speedup vs baseline: 1.6438x; 1.0237x over previous
#include <cuda_runtime.h>
#include <cuda_fp16.h>
#include <math.h>

#define DIM 2048
#define NH  16
#define HD  128
#define B2  2
#define T2  2048
#define BT  4096   // B*T
#define BH  32     // B*NH

// ---------------- device scratch ----------------
__device__ __half g_Wq[DIM*DIM];
__device__ __half g_Wk[DIM*DIM];
__device__ __half g_Wv[DIM*DIM];
__device__ __half g_Wo[DIM*DIM];
__device__ __half g_Xh[BT*DIM];      // x in fp16
__device__ __half g_Qh[BH*T2*HD];    // post-RoPE fp16 (scale folded)
__device__ __half g_Kh[BH*T2*HD];
__device__ __half g_Vt[BH*HD*T2];    // V transposed fp16 [BH][HD][T]
__device__ __half g_Y2[BT*DIM];      // attention out fp16 [BT][DIM]

// ---------------- helpers ----------------
__device__ __forceinline__ void mma16(float* d, const unsigned* a, const unsigned* b){
    asm volatile("mma.sync.aligned.m16n8k16.row.col.f32.f16.f16.f32 "
                 "{%0,%1,%2,%3},{%4,%5,%6,%7},{%8,%9},{%0,%1,%2,%3};"
                 : "+f"(d[0]),"+f"(d[1]),"+f"(d[2]),"+f"(d[3])
                 : "r"(a[0]),"r"(a[1]),"r"(a[2]),"r"(a[3]),"r"(b[0]),"r"(b[1]));
}
__device__ __forceinline__ void ldsm4(unsigned* r, unsigned addr){
    asm volatile("ldmatrix.sync.aligned.m8n8.x4.shared.b16 {%0,%1,%2,%3}, [%4];"
                 : "=r"(r[0]),"=r"(r[1]),"=r"(r[2]),"=r"(r[3]) : "r"(addr));
}

// ---------------- ternary dequant -> fp16 (all 4 weights, one launch) --------
__global__ void __launch_bounds__(256) dequant4_kernel(
    const float* __restrict__ w0, const float* __restrict__ w1,
    const float* __restrict__ w2, const float* __restrict__ w3,
    __half* __restrict__ o0, __half* __restrict__ o1,
    __half* __restrict__ o2, __half* __restrict__ o3)
{
    const float* w; __half* o;
    switch (blockIdx.y){
        case 0: w=w0; o=o0; break;
        case 1: w=w1; o=o1; break;
        case 2: w=w2; o=o2; break;
        default: w=w3; o=o3; break;
    }
    int row = blockIdx.x;
    int tid = threadIdx.x;
    const float* wr = w + (size_t)row*DIM + tid*8;
    float v[8]; float s = 0.f;
    #pragma unroll
    for (int i=0;i<8;i++){ v[i]=wr[i]; s += fabsf(v[i]); }
    #pragma unroll
    for (int off=8; off; off>>=1)
        s += __shfl_xor_sync(0xffffffffu, s, off, 16);
    float scale = fmaxf(s*(1.0f/128.0f), 1e-8f);
    float inv = 1.0f/scale;
    __half* orow = o + (size_t)row*DIM + tid*8;
    #pragma unroll
    for (int i=0;i<4;i++){
        float wn0 = v[2*i]*inv, wn1 = v[2*i+1]*inv;
        float q0 = (wn0 > 0.5f) ? 1.0f : ((wn0 < -0.5f) ? -1.0f : 0.0f);
        float q1 = (wn1 > 0.5f) ? 1.0f : ((wn1 < -0.5f) ? -1.0f : 0.0f);
        *(__half2*)(orow + 2*i) = __floats2half2_rn(q0*scale, q1*scale);
    }
}

// ---------------- f32 -> f16 convert ----------------
__global__ void __launch_bounds__(256) tohalf_kernel(
    const float* __restrict__ in, __half* __restrict__ out)
{
    size_t i = ((size_t)blockIdx.x*256 + threadIdx.x)*8;
    float4 a = *(const float4*)(in + i);
    float4 b = *(const float4*)(in + i + 4);
    __half2 h[4];
    h[0]=__floats2half2_rn(a.x,a.y); h[1]=__floats2half2_rn(a.z,a.w);
    h[2]=__floats2half2_rn(b.x,b.y); h[3]=__floats2half2_rn(b.z,b.w);
    *(uint4*)(out + i) = *(uint4*)h;
}

// ---------------- fp16 GEMM with fused epilogues -----------------------------
// C[m,n] = sum_k A[m,k]*B[n,k]; 128x128 tile, BK=64, 8 warps (2m x 4n).
// mode 0: fp32 row-major [M][N] -> Cf
// mode 2: RoPE (scale folded) -> Ch as [B][NH][T][HD]   (N-tile == one head)
// mode 3: transpose -> Ch as [B][NH][HD][T]
#define AH 72
#define GHALF (128*AH)             // halves per matrix per buffer
#define GEMM_SMEM (4*GHALF*2)      // 73728 bytes
#define SF 132                     // fp32 staging stride (words)
#define SH 130                     // fp16 staging stride (halves)

__global__ void __launch_bounds__(256) gemm_f16_kernel(
    const __half* __restrict__ A, const __half* __restrict__ Bw,
    float* __restrict__ Cf, __half* __restrict__ Ch,
    int M, int N, int K, int mode, float scale)
{
    extern __shared__ __align__(16) __half dsm[];
    __half* As = dsm;                 // 2 x [128][72]
    __half* Bs = dsm + 2*GHALF;       // 2 x [128][72]
    int tid  = threadIdx.x;
    int bm   = blockIdx.y, bn = blockIdx.x;
    int warp = tid>>5, lane = tid&31;
    int wm   = (warp&1)<<6;
    int wn   = (warp>>1)<<5;
    int g    = lane>>2, t = lane&3;

    int arow = ((lane>>3)&1)*8 + (lane&7);
    int acol = (lane>>4)*8;
    int brow = ((lane>>4)&1)*8 + (lane&7);
    int bcol = ((lane>>3)&1)*8;
    unsigned uA = (unsigned)__cvta_generic_to_shared(As);
    unsigned uB = (unsigned)__cvta_generic_to_shared(Bs);

    float acc[4][4][4];
    #pragma unroll
    for(int i=0;i<4;i++)
        #pragma unroll
        for(int j=0;j<4;j++)
            #pragma unroll
            for(int r=0;r<4;r++) acc[i][j][r]=0.f;

    int lr = tid>>2;            // 0..63
    int lc = (tid&3)<<4;        // 0,16,32,48 halves
    const __half* Ag = A  + (size_t)(bm*128 + lr)*K + lc;
    const __half* Bg = Bw + (size_t)(bn*128 + lr)*K + lc;
    int soff[2][2];
    #pragma unroll
    for(int r=0;r<2;r++)
        #pragma unroll
        for(int c=0;c<2;c++)
            soff[r][c] = (lr + r*64)*AH + lc + c*8;

    uint4 av[2][2], bv[2][2];
    #pragma unroll
    for(int r=0;r<2;r++)
        #pragma unroll
        for(int c=0;c<2;c++){
            av[r][c] = *(const uint4*)(Ag + (size_t)r*64*K + c*8);
            bv[r][c] = *(const uint4*)(Bg + (size_t)r*64*K + c*8);
        }
    #pragma unroll
    for(int r=0;r<2;r++)
        #pragma unroll
        for(int c=0;c<2;c++){
            *(uint4*)&As[soff[r][c]] = av[r][c];
            *(uint4*)&Bs[soff[r][c]] = bv[r][c];
        }

    int buf = 0;
    for(int k0=0; k0<K; k0+=64){
        __syncthreads();
        bool more = (k0+64 < K);
        if (more){
            #pragma unroll
            for(int r=0;r<2;r++)
                #pragma unroll
                for(int c=0;c<2;c++){
                    av[r][c] = *(const uint4*)(Ag + k0+64 + (size_t)r*64*K + c*8);
                    bv[r][c] = *(const uint4*)(Bg + k0+64 + (size_t)r*64*K + c*8);
                }
        }
        unsigned a_lane = uA + (buf*GHALF + (wm + arow)*AH + acol)*2;
        unsigned b_lane = uB + (buf*GHALF + (wn + brow)*AH + bcol)*2;
        #pragma unroll
        for(int ks=0;ks<4;ks++){
            unsigned af[4][4], bf[2][4];
            #pragma unroll
            for(int mi=0;mi<4;mi++)
                ldsm4(af[mi], a_lane + (mi*16*AH + ks*16)*2);
            #pragma unroll
            for(int p=0;p<2;p++)
                ldsm4(bf[p], b_lane + (p*16*AH + ks*16)*2);
            #pragma unroll
            for(int mi=0;mi<4;mi++)
                #pragma unroll
                for(int ni=0;ni<4;ni++)
                    mma16(acc[mi][ni], af[mi], &bf[ni>>1][(ni&1)*2]);
        }
        if (more){
            int nb = buf^1;
            #pragma unroll
            for(int r=0;r<2;r++)
                #pragma unroll
                for(int c=0;c<2;c++){
                    *(uint4*)&As[nb*GHALF + soff[r][c]] = av[r][c];
                    *(uint4*)&Bs[nb*GHALF + soff[r][c]] = bv[r][c];
                }
        }
        buf ^= 1;
    }

    if (mode == 0){
        #pragma unroll
        for(int mi=0;mi<4;mi++){
            #pragma unroll
            for(int ni=0;ni<4;ni++){
                int rowa = bm*128 + wm + mi*16 + g;
                int col  = bn*128 + wn + ni*8 + 2*t;
                *(float2*)(Cf + (size_t)rowa*N + col) =
                    make_float2(acc[mi][ni][0], acc[mi][ni][1]);
                *(float2*)(Cf + (size_t)(rowa+8)*N + col) =
                    make_float2(acc[mi][ni][2], acc[mi][ni][3]);
            }
        }
        return;
    }

    __syncthreads();   // all warps done reading operand smem

    int b_ = bm >> 4;
    int tb = (bm & 15) * 128;          // token base within sequence
    int h  = bn;                       // N-tile == head

    if (mode == 2){
        // stage fp32 acc: S[row][col], stride SF
        float* S = (float*)dsm;
        #pragma unroll
        for(int mi=0;mi<4;mi++){
            #pragma unroll
            for(int ni=0;ni<4;ni++){
                int row = wm + mi*16 + g;
                int col = wn + ni*8 + 2*t;
                *(float2*)&S[row*SF + col]     = make_float2(acc[mi][ni][0], acc[mi][ni][1]);
                *(float2*)&S[(row+8)*SF + col] = make_float2(acc[mi][ni][2], acc[mi][ni][3]);
            }
        }
        __syncthreads();
        __half* outp = Ch + ((size_t)(b_*NH + h)*T2 + tb)*HD;
        #pragma unroll
        for (int k=0;k<32;k++){
            int e = tid + k*256;       // 128 rows x 64 pairs
            int row = e >> 6, j = e & 63;
            float x1 = S[row*SF + j], x2 = S[row*SF + j + 64];
            float invf = exp2f(-(float)j * (13.287712379549449f/64.0f));
            float ang  = (float)(tb + row) * invf;
            float sn, cs; sincosf(ang, &sn, &cs);
            outp[(size_t)row*HD + j]      = __float2half_rn((x1*cs - x2*sn)*scale);
            outp[(size_t)row*HD + j + 64] = __float2half_rn((x1*sn + x2*cs)*scale);
        }
    } else {
        // mode 3: stage fp16, write transposed [d][t]
        __half* S = dsm;               // stride SH (odd words -> conflict-free cols)
        #pragma unroll
        for(int mi=0;mi<4;mi++){
            #pragma unroll
            for(int ni=0;ni<4;ni++){
                int row = wm + mi*16 + g;
                int col = wn + ni*8 + 2*t;
                *(__half2*)&S[row*SH + col]     = __floats2half2_rn(acc[mi][ni][0], acc[mi][ni][1]);
                *(__half2*)&S[(row+8)*SH + col] = __floats2half2_rn(acc[mi][ni][2], acc[mi][ni][3]);
            }
        }
        __syncthreads();
        __half* outp = Ch + ((size_t)(b_*NH + h)*HD)*T2 + tb;
        #pragma unroll
        for (int k=0;k<64;k++){
            int e = tid + k*256;       // 128 d x 128 t
            int d = e >> 7, tt = e & 127;
            outp[(size_t)d*T2 + tt] = S[tt*SH + d];
        }
    }
}

// ---------------- fp16 flash attention, double-buffered K/V ----------------
#define QH 136
#define VH 72
#define PH 72
#define FL_Q (128*QH)
#define FL_K (64*QH)
#define FL_V (128*VH)
#define FL_P (128*PH)
#define FL_SMEM ((FL_Q + 2*FL_K + 2*FL_V + FL_P)*2)

__global__ void __launch_bounds__(256) flash3_kernel(
    const __half* __restrict__ Q, const __half* __restrict__ K,
    const __half* __restrict__ Vt, __half* __restrict__ Y2)
{
    extern __shared__ __align__(16) __half smh[];
    __half* Qs = smh;                // [128][136]
    __half* Ks = Qs + FL_Q;          // 2 x [64][136]
    __half* Vs = Ks + 2*FL_K;        // 2 x [128][72]
    __half* Ps = Vs + 2*FL_V;        // [128][72]

    int qb  = (int)(gridDim.x - 1 - blockIdx.x);
    int bh  = blockIdx.y;
    int tid = threadIdx.x;
    int warp = tid >> 5, lane = tid & 31;
    int g = lane >> 2, t = lane & 3;

    int arow = ((lane>>3)&1)*8 + (lane&7);
    int acol = (lane>>4)*8;
    int brow = ((lane>>4)&1)*8 + (lane&7);
    int bcol = ((lane>>3)&1)*8;
    unsigned uQ = (unsigned)__cvta_generic_to_shared(Qs);
    unsigned uK = (unsigned)__cvta_generic_to_shared(Ks);
    unsigned uV = (unsigned)__cvta_generic_to_shared(Vs);
    unsigned uP = (unsigned)__cvta_generic_to_shared(Ps);
    unsigned q_lane = uQ + ((warp*16 + arow)*QH + acol)*2;
    unsigned p_lane = uP + ((warp*16 + arow)*PH + acol)*2;

    const __half* qg = Q  + ((size_t)bh*T2 + qb*128)*HD;
    const __half* kg = K  + (size_t)bh*T2*HD;
    const __half* vg = Vt + (size_t)bh*HD*T2;

    int kr = tid >> 4, kc = (tid & 15) << 3;
    int vd = tid >> 3, vc = (tid & 7) << 3;

    #pragma unroll
    for (int it=0; it<8; it++){
        int idx = tid + it*256;
        int r = idx >> 4, c = (idx & 15) << 3;
        *(uint4*)&Qs[r*QH + c] = *(const uint4*)(qg + (size_t)r*HD + c);
    }
    uint4 kvreg[8];
    #pragma unroll
    for (int it=0; it<4; it++)
        kvreg[it] = *(const uint4*)(kg + (size_t)(kr + it*16)*HD + kc);
    #pragma unroll
    for (int it=0; it<4; it++)
        kvreg[4+it] = *(const uint4*)(vg + (size_t)(vd + it*32)*T2 + vc);
    #pragma unroll
    for (int it=0; it<4; it++)
        *(uint4*)&Ks[(kr + it*16)*QH + kc] = kvreg[it];
    #pragma unroll
    for (int it=0; it<4; it++)
        *(uint4*)&Vs[(vd + it*32)*VH + vc] = kvreg[4+it];

    float m0 = -1e30f, m1 = -1e30f, l0 = 0.f, l1 = 0.f;
    float o[16][4];
    #pragma unroll
    for (int i=0;i<16;i++)
        #pragma unroll
        for (int r=0;r<4;r++) o[i][r]=0.f;

    int prow = warp*16 + g;
    int nkb = 2*qb + 2;

    for (int kb=0; kb<nkb; kb++){
        int buf = kb & 1;
        __syncthreads();
        bool more = (kb+1 < nkb);
        if (more){
            #pragma unroll
            for (int it=0; it<4; it++)
                kvreg[it] = *(const uint4*)(kg + (size_t)((kb+1)*64 + kr + it*16)*HD + kc);
            #pragma unroll
            for (int it=0; it<4; it++)
                kvreg[4+it] = *(const uint4*)(vg + (size_t)(vd + it*32)*T2 + (kb+1)*64 + vc);
        }
        unsigned k_lane = uK + (buf*FL_K + brow*QH + bcol)*2;
        unsigned v_lane = uV + (buf*FL_V + brow*VH + bcol)*2;

        float s[8][4];
        #pragma unroll
        for (int ni=0;ni<8;ni++)
            #pragma unroll
            for (int r=0;r<4;r++) s[ni][r]=0.f;
        #pragma unroll
        for (int ks=0; ks<8; ks++){
            unsigned af[4], kf[4][4];
            ldsm4(af, q_lane + ks*32);
            #pragma unroll
            for (int p=0;p<4;p++)
                ldsm4(kf[p], k_lane + (p*16*QH + ks*16)*2);
            #pragma unroll
            for (int ni=0;ni<8;ni++)
                mma16(s[ni], af, &kf[ni>>1][(ni&1)*2]);
        }

        if (kb >= 2*qb){
            int q0 = qb*128 + prow, q1 = q0 + 8;
            #pragma unroll
            for (int ni=0;ni<8;ni++){
                int k0 = kb*64 + ni*8 + 2*t;
                if (k0   > q0) s[ni][0] = -1e30f;
                if (k0+1 > q0) s[ni][1] = -1e30f;
                if (k0   > q1) s[ni][2] = -1e30f;
                if (k0+1 > q1) s[ni][3] = -1e30f;
            }
        }

        float mx0 = -1e30f, mx1 = -1e30f;
        #pragma unroll
        for (int ni=0;ni<8;ni++){
            mx0 = fmaxf(mx0, fmaxf(s[ni][0], s[ni][1]));
            mx1 = fmaxf(mx1, fmaxf(s[ni][2], s[ni][3]));
        }
        #pragma unroll
        for (int off=1; off<4; off<<=1){
            mx0 = fmaxf(mx0, __shfl_xor_sync(0xffffffffu, mx0, off, 4));
            mx1 = fmaxf(mx1, __shfl_xor_sync(0xffffffffu, mx1, off, 4));
        }
        float nm0 = fmaxf(m0, mx0), nm1 = fmaxf(m1, mx1);
        float a0 = __expf(m0 - nm0), a1 = __expf(m1 - nm1);
        m0 = nm0; m1 = nm1;
        float sum0 = 0.f, sum1 = 0.f;
        #pragma unroll
        for (int ni=0;ni<8;ni++){
            s[ni][0] = __expf(s[ni][0]-nm0); sum0 += s[ni][0];
            s[ni][1] = __expf(s[ni][1]-nm0); sum0 += s[ni][1];
            s[ni][2] = __expf(s[ni][2]-nm1); sum1 += s[ni][2];
            s[ni][3] = __expf(s[ni][3]-nm1); sum1 += s[ni][3];
        }
        #pragma unroll
        for (int off=1; off<4; off<<=1){
            sum0 += __shfl_xor_sync(0xffffffffu, sum0, off, 4);
            sum1 += __shfl_xor_sync(0xffffffffu, sum1, off, 4);
        }
        l0 = l0*a0 + sum0;
        l1 = l1*a1 + sum1;
        #pragma unroll
        for (int ti=0;ti<16;ti++){
            o[ti][0]*=a0; o[ti][1]*=a0; o[ti][2]*=a1; o[ti][3]*=a1;
        }

        #pragma unroll
        for (int ni=0;ni<8;ni++){
            int cc = ni*8 + 2*t;
            *(__half2*)&Ps[prow*PH + cc]     = __floats2half2_rn(s[ni][0], s[ni][1]);
            *(__half2*)&Ps[(prow+8)*PH + cc] = __floats2half2_rn(s[ni][2], s[ni][3]);
        }
        __syncwarp();

        #pragma unroll
        for (int ks=0; ks<4; ks++){
            unsigned af[4], vf[8][4];
            ldsm4(af, p_lane + ks*32);
            #pragma unroll
            for (int p=0;p<8;p++)
                ldsm4(vf[p], v_lane + (p*16*VH + ks*16)*2);
            #pragma unroll
            for (int ti=0;ti<16;ti++)
                mma16(o[ti], af, &vf[ti>>1][(ti&1)*2]);
        }

        if (more){
            int nb = buf^1;
            #pragma unroll
            for (int it=0; it<4; it++)
                *(uint4*)&Ks[nb*FL_K + (kr + it*16)*QH + kc] = kvreg[it];
            #pragma unroll
            for (int it=0; it<4; it++)
                *(uint4*)&Vs[nb*FL_V + (vd + it*32)*VH + vc] = kvreg[4+it];
        }
    }

    float i0 = 1.0f/l0, i1 = 1.0f/l1;
    int trow = qb*128 + prow;
    int b_ = bh >> 4, h = bh & 15;
    __half* yr = Y2 + ((size_t)b_*T2)*DIM + h*HD;
    #pragma unroll
    for (int ti=0;ti<16;ti++){
        int col = ti*8 + 2*t;
        *(__half2*)(yr + (size_t)trow*DIM + col) =
            __floats2half2_rn(o[ti][0]*i0, o[ti][1]*i0);
        *(__half2*)(yr + (size_t)(trow+8)*DIM + col) =
            __floats2half2_rn(o[ti][2]*i1, o[ti][3]*i1);
    }
}

// ---------------- launch ----------------
extern "C" void kernel_launch(void* const* d_in, const int* in_sizes, int n_in,
                              void* d_out, int out_size)
{
    const float* x  = (const float*)d_in[0];
    const float* wq = (const float*)d_in[1];
    const float* wk = (const float*)d_in[2];
    const float* wv = (const float*)d_in[3];
    const float* wo = (const float*)d_in[4];
    float* out = (float*)d_out;

    __half *Wq,*Wk,*Wv,*Wo,*Xh,*Qh,*Kh,*Vt,*Y2;
    cudaGetSymbolAddress((void**)&Wq, g_Wq);
    cudaGetSymbolAddress((void**)&Wk, g_Wk);
    cudaGetSymbolAddress((void**)&Wv, g_Wv);
    cudaGetSymbolAddress((void**)&Wo, g_Wo);
    cudaGetSymbolAddress((void**)&Xh, g_Xh);
    cudaGetSymbolAddress((void**)&Qh, g_Qh);
    cudaGetSymbolAddress((void**)&Kh, g_Kh);
    cudaGetSymbolAddress((void**)&Vt, g_Vt);
    cudaGetSymbolAddress((void**)&Y2, g_Y2);

    cudaFuncSetAttribute(gemm_f16_kernel,
        cudaFuncAttributeMaxDynamicSharedMemorySize, GEMM_SMEM);
    cudaFuncSetAttribute(flash3_kernel,
        cudaFuncAttributeMaxDynamicSharedMemorySize, FL_SMEM);

    dequant4_kernel<<<dim3(DIM,4),256>>>(wq, wk, wv, wo, Wq, Wk, Wv, Wo);
    tohalf_kernel<<<(BT*DIM)/2048, 256>>>(x, Xh);

    dim3 gg(DIM/128, BT/128);
    gemm_f16_kernel<<<gg,256,GEMM_SMEM>>>(Xh, Wq, 0, Qh, BT, DIM, DIM, 2,
                                          0.08838834764831845f);
    gemm_f16_kernel<<<gg,256,GEMM_SMEM>>>(Xh, Wk, 0, Kh, BT, DIM, DIM, 2, 1.0f);
    gemm_f16_kernel<<<gg,256,GEMM_SMEM>>>(Xh, Wv, 0, Vt, BT, DIM, DIM, 3, 1.0f);

    flash3_kernel<<<dim3(T2/128, BH), 256, FL_SMEM>>>(Qh, Kh, Vt, Y2);

    gemm_f16_kernel<<<gg,256,GEMM_SMEM>>>(Y2, Wo, out, 0, BT, DIM, DIM, 0, 1.0f);
}